// round 13
// baseline (speedup 1.0000x reference)
#include <cuda_runtime.h>
#include <cuda_fp16.h>

#define B_   2
#define H_   8
#define L_   2048
#define DH_  64
#define D_   512
#define M_   4096
#define NQKV 1536
#define D2   256                 // uints (half2) per row of a D_-wide matrix
#define QS_U 1048576             // uints per qkv section: B*H*L*DH/2
#define LOG2E 1.4426950408889634f

// Scratch (device globals; no allocations allowed). ALL layouts PLAIN
// (ldmatrix handles fragment shuffling).
// q (prescaled by 0.125*log2e), k: [B,H,L, 32 uints]
// v: transposed per 64-key tile [B,H,L/64, 64 dh rows, 64 key halves]
__device__ unsigned g_qkv[3 * QS_U];
__device__ unsigned g_ao[M_ * D2];       // attn out (plain)
__device__ unsigned g_xt[M_ * D2];       // x converted
__device__ unsigned g_w1[NQKV * D2];     // w_qkv converted
__device__ unsigned g_w2[D_ * D2];       // w_out converted

__device__ __forceinline__ unsigned pk2(float a, float b) {
    __half2 h = __floats2half2_rn(a, b);       // low = a
    return *(unsigned*)&h;
}
__device__ __forceinline__ unsigned pkcvt(float hi, float lo) {
    unsigned r; asm("cvt.rn.f16x2.f32 %0, %1, %2;" : "=r"(r) : "f"(hi), "f"(lo)); return r;
}
__device__ __forceinline__ unsigned ex2h2(unsigned x) {
    unsigned r; asm("ex2.approx.f16x2 %0, %1;" : "=r"(r) : "r"(x)); return r;
}
__device__ __forceinline__ float ex2(float x) {
    float r; asm("ex2.approx.f32 %0, %1;" : "=f"(r) : "f"(x)); return r;
}
__device__ __forceinline__ unsigned sptr(const void* p) {
    return (unsigned)__cvta_generic_to_shared(p);
}
__device__ __forceinline__ void ldsm4(unsigned& d0, unsigned& d1, unsigned& d2, unsigned& d3,
                                      unsigned addr) {
    asm volatile("ldmatrix.sync.aligned.m8n8.x4.shared.b16 {%0,%1,%2,%3}, [%4];"
                 : "=r"(d0), "=r"(d1), "=r"(d2), "=r"(d3) : "r"(addr));
}
#define CP16(d, s) asm volatile("cp.async.cg.shared.global [%0], [%1], 16;" :: "r"(d), "l"(s) : "memory")
__device__ __forceinline__ void cp_commit() { asm volatile("cp.async.commit_group;" ::: "memory"); }
__device__ __forceinline__ void cp_wait0()  { asm volatile("cp.async.wait_group 0;" ::: "memory"); }
__device__ __forceinline__ void cp_wait1()  { asm volatile("cp.async.wait_group 1;" ::: "memory"); }

__device__ __forceinline__ void mma16(float* c,
                                      unsigned a0, unsigned a1, unsigned a2, unsigned a3,
                                      unsigned b0, unsigned b1) {
    asm volatile("mma.sync.aligned.m16n8k16.row.col.f32.f16.f16.f32 "
                 "{%0,%1,%2,%3}, {%4,%5,%6,%7}, {%8,%9}, {%0,%1,%2,%3};"
                 : "+f"(c[0]), "+f"(c[1]), "+f"(c[2]), "+f"(c[3])
                 : "r"(a0), "r"(a1), "r"(a2), "r"(a3), "r"(b0), "r"(b1));
}

// ---------------------------------------------------------------------------
// Fused prepass: fp32 -> half2 plain convert for x, w_qkv, w_out (one launch).
// ---------------------------------------------------------------------------
#define N16_X  (M_ * D_ / 16)
#define N16_W1 (NQKV * D_ / 16)
#define N16_W2 (D_ * D_ / 16)
#define N16_TOT (N16_X + N16_W1 + N16_W2)

__global__ __launch_bounds__(256) void prep_all(const float* __restrict__ x,
                                                const float* __restrict__ wqkv,
                                                const float* __restrict__ wout)
{
    int i = blockIdx.x * blockDim.x + threadIdx.x;
    if (i >= N16_TOT) return;
    const float* src;
    unsigned* dst;
    if (i < N16_X)                { src = x    + (size_t)i * 16;            dst = g_xt + (size_t)i * 8; }
    else if (i < N16_X + N16_W1)  { size_t j = i - N16_X;
                                    src = wqkv + j * 16;                     dst = g_w1 + j * 8; }
    else                          { size_t j = i - N16_X - N16_W1;
                                    src = wout + j * 16;                     dst = g_w2 + j * 8; }
    const float4* s = (const float4*)src;
    float4 s0 = s[0], s1 = s[1], s2 = s[2], s3 = s[3];
    uint4 o0, o1;
    o0.x = pk2(s0.x, s0.y); o0.y = pk2(s0.z, s0.w);
    o0.z = pk2(s1.x, s1.y); o0.w = pk2(s1.z, s1.w);
    o1.x = pk2(s2.x, s2.y); o1.y = pk2(s2.z, s2.w);
    o1.z = pk2(s3.x, s3.y); o1.w = pk2(s3.z, s3.w);
    uint4* d = (uint4*)dst;
    d[0] = o0; d[1] = o1;
}

// ---------------------------------------------------------------------------
// fp16 GEMM (256 threads, 8 warps 4x2, warp tile 32x64), 3-stage cp.async
// pipeline with a single __syncthreads per k-chunk, ldmatrix fragments.
// EPI=0: scatter qkv PLAIN.  EPI=1: A := g_ao, write out + bias fp32.
// ---------------------------------------------------------------------------
#define GP 36
#define GEMM_SMEM (3 * 2 * 128 * GP * 4)

template <int NTOT, int EPI>
__global__ __launch_bounds__(256, 2) void gemm_h(const unsigned* __restrict__ A,
                                                 const unsigned* __restrict__ Wt,
                                                 const float* __restrict__ bias,
                                                 float* __restrict__ out)
{
    extern __shared__ unsigned gsm[];
    unsigned* As = gsm;                 // [3][128][GP]
    unsigned* Bs = gsm + 3 * 128 * GP;  // [3][128][GP]

    const int m0 = blockIdx.y * 128;
    const int n0 = blockIdx.x * 128;
    const int tid  = threadIdx.x;
    const int warp = tid >> 5, lane = tid & 31;
    const int g = lane >> 2, t = lane & 3;
    const int wm = warp >> 1, wn = warp & 1;

    const int arow = ((lane >> 3) & 1) * 8 + (lane & 7);
    const int acol = (lane >> 4) << 2;                    // uints
    const int brow = ((lane >> 4) << 3) + (lane & 7);
    const int bcol = ((lane >> 3) & 1) * 4;               // uints

    const unsigned* Ap = (EPI == 1) ? (const unsigned*)g_ao : A;

    float C[2][8][4] = {};

    auto issue = [&](int ki, int buf) {
        int k0 = ki * 32;                       // uints
        unsigned* Ad = As + buf * 128 * GP;
        unsigned* Bd = Bs + buf * 128 * GP;
        #pragma unroll
        for (int p = 0; p < 4; p++) {
            int c = tid + p * 256;
            int r = c >> 3, col = (c & 7) * 4;
            CP16(sptr(&Ad[r * GP + col]), &Ap[(size_t)(m0 + r) * D2 + k0 + col]);
            CP16(sptr(&Bd[r * GP + col]), &Wt[(size_t)(n0 + r) * D2 + k0 + col]);
        }
    };

    issue(0, 0); cp_commit();
    issue(1, 1); cp_commit();

    int buf = 0;
    for (int ki = 0; ki < 8; ki++) {
        // stage ki ready (allow ki+1 in flight); barrier also certifies all
        // warps done with chunk ki-1, whose stage (ki+2)%3 we overwrite below.
        cp_wait1();
        __syncthreads();

        const unsigned* Af = As + buf * 128 * GP;
        const unsigned* Bf = Bs + buf * 128 * GP;
        #pragma unroll
        for (int ks = 0; ks < 4; ks++) {         // 4 k16 steps per chunk
            unsigned a[2][4];
            #pragma unroll
            for (int mf = 0; mf < 2; mf++)
                ldsm4(a[mf][0], a[mf][1], a[mf][2], a[mf][3],
                      sptr(&Af[(wm * 32 + mf * 16 + arow) * GP + ks * 8 + acol]));
            #pragma unroll
            for (int f = 0; f < 4; f++) {
                unsigned d0, d1, d2, d3;
                ldsm4(d0, d1, d2, d3,
                      sptr(&Bf[(wn * 64 + 16 * f + brow) * GP + ks * 8 + bcol]));
                mma16(C[0][2*f],   a[0][0], a[0][1], a[0][2], a[0][3], d0, d1);
                mma16(C[0][2*f+1], a[0][0], a[0][1], a[0][2], a[0][3], d2, d3);
                mma16(C[1][2*f],   a[1][0], a[1][1], a[1][2], a[1][3], d0, d1);
                mma16(C[1][2*f+1], a[1][0], a[1][1], a[1][2], a[1][3], d2, d3);
            }
        }

        if (ki + 2 < 8) {
            int nb = buf + 2; if (nb >= 3) nb -= 3;
            issue(ki + 2, nb);
        }
        cp_commit();
        if (++buf == 3) buf = 0;
    }

    const float qscale = 0.125f * LOG2E;

    if (EPI == 0) {
        __half* hv = (__half*)g_qkv;
        #pragma unroll
        for (int mf = 0; mf < 2; mf++) {
            int m = m0 + wm * 32 + mf * 16;
            #pragma unroll
            for (int nf = 0; nf < 8; nf++) {
                int n   = n0 + wn * 64 + nf * 8 + 2 * t;
                int sec = n >> 9;
                int h   = (n >> 6) & 7;
                int dh  = n & 63;
                #pragma unroll
                for (int rr = 0; rr < 2; rr++) {
                    int mm = m + g + rr * 8;
                    int b  = mm >> 11;
                    int l  = mm & 2047;
                    float c0v = C[mf][nf][rr * 2 + 0];
                    float c1v = C[mf][nf][rr * 2 + 1];
                    if (sec == 0) { c0v *= qscale; c1v *= qscale; }
                    if (sec < 2) {
                        g_qkv[(size_t)sec * QS_U
                              + (size_t)((b * H_ + h) * L_ + l) * 32 + (dh >> 1)] = pk2(c0v, c1v);
                    } else {
                        size_t vb2 = (size_t)2 * QS_U * 2
                                   + (size_t)(b * H_ + h) * L_ * DH_
                                   + (size_t)(l >> 6) * 4096 + (l & 63);
                        hv[vb2 + (size_t)dh * 64]       = __float2half_rn(c0v);
                        hv[vb2 + (size_t)(dh + 1) * 64] = __float2half_rn(c1v);
                    }
                }
            }
        }
    } else {
        #pragma unroll
        for (int mf = 0; mf < 2; mf++) {
            int m = m0 + wm * 32 + mf * 16;
            #pragma unroll
            for (int nf = 0; nf < 8; nf++) {
                int n = n0 + wn * 64 + nf * 8 + 2 * t;
                float b0v = bias[n], b1v = bias[n + 1];
                #pragma unroll
                for (int rr = 0; rr < 2; rr++) {
                    int mm = m + g + rr * 8;
                    float2 v;
                    v.x = C[mf][nf][rr * 2 + 0] + b0v;
                    v.y = C[mf][nf][rr * 2 + 1] + b1v;
                    *(float2*)&out[(size_t)mm * NTOT + n] = v;
                }
            }
        }
    }
}

// ---------------------------------------------------------------------------
// Flash attention: 4-stage cp.async pipeline, single __syncthreads per tile,
// DELAYED PV (PV of tile jt-1 issued in the same mma block as S of tile jt;
// O rescaled AFTER the PV add, which keeps the recurrence exact).
// ---------------------------------------------------------------------------
#define KP 36
#define ATTN_SMEM ((8 * 64 * KP + 128 * KP) * 4 + 128 * 8 + 2 * 64 * 16)

__global__ __launch_bounds__(256, 2) void attn_h(const float* __restrict__ pos,
                                                 const float* __restrict__ log_sigma,
                                                 const float* __restrict__ gbias_p,
                                                 const int*   __restrict__ nsp)
{
    extern __shared__ unsigned smA[];
    unsigned* Ks = smA;                   // [4][64][KP]
    unsigned* Vs = smA + 4 * 64 * KP;     // [4][64][KP]  (V^T tiles)
    unsigned* Qs = smA + 8 * 64 * KP;     // [128][KP]
    float2* qpos = (float2*)(Qs + 128 * KP);     // 128
    float4* kq   = (float4*)(qpos + 128);        // [2][64]: kx, ky, nc2*|p|^2, 0

    const int i0 = blockIdx.x * 128;
    const int bh = blockIdx.y;
    const int b  = bh >> 3, h = bh & 7;
    const int Ls = *nsp;
    const float gb2 = (*gbias_p) * LOG2E;
    const float nc2 = -0.5f * __expf(-2.0f * log_sigma[h]) * LOG2E;

    const int tid  = threadIdx.x;
    const int warp = tid >> 5, lane = tid & 31;
    const int g = lane >> 2, t = lane & 3;
    const int wr = warp * 16;

    const unsigned* qb = g_qkv + (size_t)(b * H_ + h) * L_ * 32;
    const unsigned* kb = g_qkv + (size_t)QS_U + (size_t)(b * H_ + h) * L_ * 32;
    const unsigned* vb = g_qkv + 2 * (size_t)QS_U + (size_t)(b * H_ + h) * L_ * 32;

    // Stage Q tile + qpos + kq tile 0
    #pragma unroll
    for (int p = 0; p < 4; p++) {
        int c = tid + p * 256;
        int r = c >> 3, c4 = (c & 7) * 4;
        *(uint4*)&Qs[r * KP + c4] = *(const uint4*)&qb[(size_t)(i0 + r) * 32 + c4];
    }
    if (tid < 128) {
        int iG = i0 + tid;
        float2 v = make_float2(0.f, 0.f);
        if (iG < Ls) v = *(const float2*)&pos[(size_t)(b * Ls + iG) * 2];
        qpos[tid] = v;
    }
    if (tid < 64) {
        float2 p = make_float2(0.f, 0.f);
        if (tid < Ls) p = *(const float2*)&pos[(size_t)(b * Ls + tid) * 2];
        kq[tid] = make_float4(p.x, p.y, nc2 * (p.x * p.x + p.y * p.y), 0.f);
    }

    auto issue = [&](int jt, int buf) {
        const unsigned* kt = kb + (size_t)jt * 2048;
        const unsigned* vt = vb + (size_t)jt * 2048;
        unsigned* Kd = Ks + buf * 64 * KP;
        unsigned* Vd = Vs + buf * 64 * KP;
        #pragma unroll
        for (int p = 0; p < 2; p++) {
            int c = tid + p * 256;
            int r = c >> 3, c4 = (c & 7) * 4;
            CP16(sptr(&Kd[r * KP + c4]), kt + r * 32 + c4);
            CP16(sptr(&Vd[r * KP + c4]), vt + r * 32 + c4);
        }
    };

    // Prologue: fill stages 0 and 1
    issue(0, 0); cp_commit();
    issue(1, 1); cp_commit();

    __syncthreads();   // Qs/qpos/kq visible

    // Q A-fragments via ldmatrix (once)
    unsigned qf[4][4];
    {
        int qrow = wr + ((lane >> 3) & 1) * 8 + (lane & 7);
        int qcol = (lane >> 4) << 2;
        #pragma unroll
        for (int ks = 0; ks < 4; ks++)
            ldsm4(qf[ks][0], qf[ks][1], qf[ks][2], qf[ks][3],
                  sptr(&Qs[qrow * KP + ks * 8 + qcol]));
    }

    // Row constants for factored bias
    float cx0, cy0, cx1, cy1, ga0, ga1;
    bool iin0, iin1;
    {
        int r0 = i0 + wr + g;
        float2 p0 = qpos[wr + g], p1 = qpos[wr + g + 8];
        cx0 = -2.f * nc2 * p0.x; cy0 = -2.f * nc2 * p0.y;
        cx1 = -2.f * nc2 * p1.x; cy1 = -2.f * nc2 * p1.y;
        ga0 = gb2 - nc2 * (p0.x * p0.x + p0.y * p0.y);
        ga1 = gb2 - nc2 * (p1.x * p1.x + p1.y * p1.y);
        iin0 = r0 < Ls; iin1 = (r0 + 8) < Ls;
    }

    const int lrow8 = ((lane >> 4) << 3) + (lane & 7);
    const int lsel  = ((lane >> 3) & 1) * 4;

    float O[8][4] = {};
    float O8[4] = {};
    float m0 = -1e30f, m1 = -1e30f;
    const bool i_allsp = (i0 + 128) <= Ls;
    const bool i_allout = i0 >= Ls;
    const unsigned ones2 = (g == 0) ? 0x3C003C00u : 0u;

    unsigned ph[8], phh[8];          // P fragments of the PREVIOUS tile
    int buf = 0;                     // stage of tile jt (= jt % 4)

    for (int jt = 0; jt < 32; jt++) {
        // Single barrier: stage jt visible; all warps finished tile jt-1,
        // so stage (jt+2)%4 (holding tile jt-2) is safe to overwrite below.
        cp_wait1();
        __syncthreads();

        bool pref = (jt + 1 < 32);
        float2 pp = make_float2(0.f, 0.f);
        if (pref && tid < 64) {
            int jG = (jt + 1) * 64 + tid;
            if (jG < Ls) pp = *(const float2*)&pos[(size_t)(b * Ls + jG) * 2];
        }

        const unsigned* Kf = Ks + buf * 64 * KP;
        const int pbuf = (buf == 0) ? 3 : buf - 1;
        const unsigned* Vf = Vs + pbuf * 64 * KP;   // V of tile jt-1
        const float4*   kc = kq + (jt & 1) * 64;
        const int j0 = jt * 64;

        // ---- fused mma block: S(jt) and PV(jt-1), fully independent ----
        float S[8][4] = {};
        #pragma unroll
        for (int f = 0; f < 4; f++) {
            #pragma unroll
            for (int ks = 0; ks < 4; ks++) {
                unsigned d0, d1, d2, d3;
                ldsm4(d0, d1, d2, d3,
                      sptr(&Kf[(16 * f + lrow8) * KP + 8 * ks + lsel]));
                mma16(S[2*f],   qf[ks][0], qf[ks][1], qf[ks][2], qf[ks][3], d0, d1);
                mma16(S[2*f+1], qf[ks][0], qf[ks][1], qf[ks][2], qf[ks][3], d2, d3);
            }
        }
        if (jt > 0) {
            #pragma unroll
            for (int f = 0; f < 4; f++) {
                #pragma unroll
                for (int ks = 0; ks < 4; ks++) {
                    unsigned d0, d1, d2, d3;
                    ldsm4(d0, d1, d2, d3,
                          sptr(&Vf[(16 * f + lrow8) * KP + 8 * ks + lsel]));
                    mma16(O[2*f],   ph[2*ks], phh[2*ks], ph[2*ks+1], phh[2*ks+1], d0, d1);
                    mma16(O[2*f+1], ph[2*ks], phh[2*ks], ph[2*ks+1], phh[2*ks+1], d2, d3);
                }
            }
            #pragma unroll
            for (int ks = 0; ks < 4; ks++)
                mma16(O8, ph[2*ks], phh[2*ks], ph[2*ks+1], phh[2*ks+1], ones2, ones2);
        }

        // Factored bias (scores shifted by -nc2|pi|^2; softmax-invariant)
        if (i_allsp && (j0 + 64) <= Ls) {
            #pragma unroll
            for (int nf = 0; nf < 8; nf++) {
                int c0 = nf * 8 + 2 * t;
                float4 k0 = kc[c0], k1 = kc[c0 + 1];
                S[nf][0] = fmaf(cx0, k0.x, fmaf(cy0, k0.y, S[nf][0] + k0.z));
                S[nf][1] = fmaf(cx0, k1.x, fmaf(cy0, k1.y, S[nf][1] + k1.z));
                S[nf][2] = fmaf(cx1, k0.x, fmaf(cy1, k0.y, S[nf][2] + k0.z));
                S[nf][3] = fmaf(cx1, k1.x, fmaf(cy1, k1.y, S[nf][3] + k1.z));
            }
        } else if (j0 >= Ls || i_allout) {
            #pragma unroll
            for (int nf = 0; nf < 8; nf++) {
                S[nf][0] += ga0; S[nf][1] += ga0; S[nf][2] += ga1; S[nf][3] += ga1;
            }
        } else {
            #pragma unroll
            for (int nf = 0; nf < 8; nf++) {
                int c0 = nf * 8 + 2 * t;
                int jg0 = j0 + c0;
                float4 k0 = kc[c0], k1 = kc[c0 + 1];
                bool jin0 = jg0 < Ls, jin1 = (jg0 + 1) < Ls;
                S[nf][0] = (iin0 && jin0)
                    ? fmaf(cx0, k0.x, fmaf(cy0, k0.y, S[nf][0] + k0.z)) : S[nf][0] + ga0;
                S[nf][1] = (iin0 && jin1)
                    ? fmaf(cx0, k1.x, fmaf(cy0, k1.y, S[nf][1] + k1.z)) : S[nf][1] + ga0;
                S[nf][2] = (iin1 && jin0)
                    ? fmaf(cx1, k0.x, fmaf(cy1, k0.y, S[nf][2] + k0.z)) : S[nf][2] + ga1;
                S[nf][3] = (iin1 && jin1)
                    ? fmaf(cx1, k1.x, fmaf(cy1, k1.y, S[nf][3] + k1.z)) : S[nf][3] + ga1;
            }
        }

        // Online softmax (base 2). O now includes PV through tile jt-1 in
        // m(jt-1) units — rescale AFTER the PV add (exact recurrence).
        float mx0 = -1e30f, mx1 = -1e30f;
        #pragma unroll
        for (int nf = 0; nf < 8; nf++) {
            mx0 = fmaxf(mx0, fmaxf(S[nf][0], S[nf][1]));
            mx1 = fmaxf(mx1, fmaxf(S[nf][2], S[nf][3]));
        }
        mx0 = fmaxf(mx0, __shfl_xor_sync(0xffffffffu, mx0, 1));
        mx0 = fmaxf(mx0, __shfl_xor_sync(0xffffffffu, mx0, 2));
        mx1 = fmaxf(mx1, __shfl_xor_sync(0xffffffffu, mx1, 1));
        mx1 = fmaxf(mx1, __shfl_xor_sync(0xffffffffu, mx1, 2));
        float mn0 = fmaxf(m0, mx0), mn1 = fmaxf(m1, mx1);
        bool stay = (mn0 == m0) && (mn1 == m1);
        if (!__all_sync(0xffffffffu, stay)) {
            float a0 = ex2(m0 - mn0), a1 = ex2(m1 - mn1);
            #pragma unroll
            for (int df = 0; df < 8; df++) {
                O[df][0] *= a0; O[df][1] *= a0; O[df][2] *= a1; O[df][3] *= a1;
            }
            O8[0] *= a0; O8[1] *= a0; O8[2] *= a1; O8[3] *= a1;
        }
        m0 = mn0; m1 = mn1;

        // P(jt) = 2^(S-m) packed half2 — becomes next iteration's PV operand
        #pragma unroll
        for (int nf = 0; nf < 8; nf++) {
            float e0 = S[nf][0] - m0, e1 = S[nf][1] - m0;
            float e2 = S[nf][2] - m1, e3 = S[nf][3] - m1;
            ph[nf]  = ex2h2(pkcvt(e1, e0));
            phh[nf] = ex2h2(pkcvt(e3, e2));
        }

        // publish next tile's kq (read at jt+1 after its top barrier)
        if (pref && tid < 64)
            kq[((jt + 1) & 1) * 64 + tid] =
                make_float4(pp.x, pp.y, nc2 * (pp.x * pp.x + pp.y * pp.y), 0.f);

        // issue stage jt+2 (overwrites tile jt-2's stage; all warps passed
        // this tile's barrier after consuming it). Unconditional commit
        // keeps the group count uniform for cp_wait1.
        if (jt + 2 < 32) {
            int nb = buf + 2; if (nb >= 4) nb -= 4;
            issue(jt + 2, nb);
        }
        cp_commit();

        if (++buf == 4) buf = 0;
    }

    // Epilogue: pending PV of tile 31 (stage 31 % 4 = 3; never overwritten)
    {
        const unsigned* Vf = Vs + 3 * 64 * KP;
        #pragma unroll
        for (int f = 0; f < 4; f++) {
            #pragma unroll
            for (int ks = 0; ks < 4; ks++) {
                unsigned d0, d1, d2, d3;
                ldsm4(d0, d1, d2, d3,
                      sptr(&Vf[(16 * f + lrow8) * KP + 8 * ks + lsel]));
                mma16(O[2*f],   ph[2*ks], phh[2*ks], ph[2*ks+1], phh[2*ks+1], d0, d1);
                mma16(O[2*f+1], ph[2*ks], phh[2*ks], ph[2*ks+1], phh[2*ks+1], d2, d3);
            }
        }
        #pragma unroll
        for (int ks = 0; ks < 4; ks++)
            mma16(O8, ph[2*ks], phh[2*ks], ph[2*ks+1], phh[2*ks+1], ones2, ones2);
    }

    // l from t=0 lane of each quad; normalize; write g_ao PLAIN
    float l0 = __shfl_sync(0xffffffffu, O8[0], lane & ~3);
    float l1 = __shfl_sync(0xffffffffu, O8[2], lane & ~3);
    float il0 = 1.f / l0, il1 = 1.f / l1;
    int r0 = i0 + wr + g, r1 = r0 + 8;
    #pragma unroll
    for (int df = 0; df < 8; df++) {
        int col = df * 4 + t;
        g_ao[(size_t)(b * L_ + r0) * D2 + h * 32 + col] = pk2(O[df][0] * il0, O[df][1] * il0);
        g_ao[(size_t)(b * L_ + r1) * D2 + h * 32 + col] = pk2(O[df][2] * il1, O[df][3] * il1);
    }
}

// ---------------------------------------------------------------------------
extern "C" void kernel_launch(void* const* d_in, const int* in_sizes, int n_in,
                              void* d_out, int out_size)
{
    const float* x     = (const float*)d_in[0];
    const float* pos   = (const float*)d_in[1];
    const float* wqkv  = (const float*)d_in[2];
    const float* wout  = (const float*)d_in[3];
    const float* bout  = (const float*)d_in[4];
    const float* lsig  = (const float*)d_in[5];
    const float* gbias = (const float*)d_in[6];
    const int*   nsp   = (const int*)d_in[7];
    float* out = (float*)d_out;

    unsigned *p_xt, *p_w1, *p_w2;
    cudaGetSymbolAddress((void**)&p_xt, g_xt);
    cudaGetSymbolAddress((void**)&p_w1, g_w1);
    cudaGetSymbolAddress((void**)&p_w2, g_w2);

    cudaFuncSetAttribute(attn_h, cudaFuncAttributeMaxDynamicSharedMemorySize, ATTN_SMEM);
    cudaFuncSetAttribute(gemm_h<NQKV, 0>, cudaFuncAttributeMaxDynamicSharedMemorySize, GEMM_SMEM);
    cudaFuncSetAttribute(gemm_h<D_, 1>, cudaFuncAttributeMaxDynamicSharedMemorySize, GEMM_SMEM);

    prep_all<<<(N16_TOT + 255) / 256, 256>>>(x, wqkv, wout);
    gemm_h<NQKV, 0><<<dim3(NQKV / 128, M_ / 128), 256, GEMM_SMEM>>>(p_xt, p_w1, nullptr, nullptr);
    attn_h<<<dim3(L_ / 128, B_ * H_), 256, ATTN_SMEM>>>(pos, lsig, gbias, nsp);
    gemm_h<D_, 1><<<dim3(D_ / 128, M_ / 128), 256, GEMM_SMEM>>>(nullptr, p_w2, bout, out);
}

// round 14
// speedup vs baseline: 1.0019x; 1.0019x over previous
#include <cuda_runtime.h>
#include <cuda_fp16.h>

#define B_   2
#define H_   8
#define L_   2048
#define DH_  64
#define D_   512
#define M_   4096
#define NQKV 1536
#define D2   256                 // uints (half2) per row of a D_-wide matrix
#define QS_U 1048576             // uints per qkv section: B*H*L*DH/2
#define LOG2E 1.4426950408889634f

// Scratch (device globals; no allocations allowed). ALL layouts PLAIN
// (ldmatrix handles fragment shuffling).
// q (prescaled by 0.125*log2e), k: [B,H,L, 32 uints]
// v: transposed per 64-key tile [B,H,L/64, 64 dh rows, 64 key halves]
__device__ unsigned g_qkv[3 * QS_U];
__device__ unsigned g_ao[M_ * D2];       // attn out (plain)
__device__ unsigned g_xt[M_ * D2];       // x converted
__device__ unsigned g_w1[NQKV * D2];     // w_qkv converted
__device__ unsigned g_w2[D_ * D2];       // w_out converted

__device__ __forceinline__ unsigned pk2(float a, float b) {
    __half2 h = __floats2half2_rn(a, b);       // low = a
    return *(unsigned*)&h;
}
__device__ __forceinline__ unsigned pkcvt(float hi, float lo) {
    unsigned r; asm("cvt.rn.f16x2.f32 %0, %1, %2;" : "=r"(r) : "f"(hi), "f"(lo)); return r;
}
__device__ __forceinline__ unsigned ex2h2(unsigned x) {
    unsigned r; asm("ex2.approx.f16x2 %0, %1;" : "=r"(r) : "r"(x)); return r;
}
__device__ __forceinline__ float ex2(float x) {
    float r; asm("ex2.approx.f32 %0, %1;" : "=f"(r) : "f"(x)); return r;
}
__device__ __forceinline__ unsigned sptr(const void* p) {
    return (unsigned)__cvta_generic_to_shared(p);
}
__device__ __forceinline__ void ldsm4(unsigned& d0, unsigned& d1, unsigned& d2, unsigned& d3,
                                      unsigned addr) {
    asm volatile("ldmatrix.sync.aligned.m8n8.x4.shared.b16 {%0,%1,%2,%3}, [%4];"
                 : "=r"(d0), "=r"(d1), "=r"(d2), "=r"(d3) : "r"(addr));
}
#define CP16(d, s) asm volatile("cp.async.cg.shared.global [%0], [%1], 16;" :: "r"(d), "l"(s) : "memory")
__device__ __forceinline__ void cp_commit() { asm volatile("cp.async.commit_group;" ::: "memory"); }
__device__ __forceinline__ void cp_wait0()  { asm volatile("cp.async.wait_group 0;" ::: "memory"); }
__device__ __forceinline__ void cp_wait1()  { asm volatile("cp.async.wait_group 1;" ::: "memory"); }

__device__ __forceinline__ void mma16(float* c,
                                      unsigned a0, unsigned a1, unsigned a2, unsigned a3,
                                      unsigned b0, unsigned b1) {
    asm volatile("mma.sync.aligned.m16n8k16.row.col.f32.f16.f16.f32 "
                 "{%0,%1,%2,%3}, {%4,%5,%6,%7}, {%8,%9}, {%0,%1,%2,%3};"
                 : "+f"(c[0]), "+f"(c[1]), "+f"(c[2]), "+f"(c[3])
                 : "r"(a0), "r"(a1), "r"(a2), "r"(a3), "r"(b0), "r"(b1));
}

// ---------------------------------------------------------------------------
// Fused prepass: fp32 -> half2 plain convert for x, w_qkv, w_out (one launch).
// ---------------------------------------------------------------------------
#define N16_X  (M_ * D_ / 16)
#define N16_W1 (NQKV * D_ / 16)
#define N16_W2 (D_ * D_ / 16)
#define N16_TOT (N16_X + N16_W1 + N16_W2)

__global__ __launch_bounds__(256) void prep_all(const float* __restrict__ x,
                                                const float* __restrict__ wqkv,
                                                const float* __restrict__ wout)
{
    int i = blockIdx.x * blockDim.x + threadIdx.x;
    if (i >= N16_TOT) return;
    const float* src;
    unsigned* dst;
    if (i < N16_X)                { src = x    + (size_t)i * 16;            dst = g_xt + (size_t)i * 8; }
    else if (i < N16_X + N16_W1)  { size_t j = i - N16_X;
                                    src = wqkv + j * 16;                     dst = g_w1 + j * 8; }
    else                          { size_t j = i - N16_X - N16_W1;
                                    src = wout + j * 16;                     dst = g_w2 + j * 8; }
    const float4* s = (const float4*)src;
    float4 s0 = s[0], s1 = s[1], s2 = s[2], s3 = s[3];
    uint4 o0, o1;
    o0.x = pk2(s0.x, s0.y); o0.y = pk2(s0.z, s0.w);
    o0.z = pk2(s1.x, s1.y); o0.w = pk2(s1.z, s1.w);
    o1.x = pk2(s2.x, s2.y); o1.y = pk2(s2.z, s2.w);
    o1.z = pk2(s3.x, s3.y); o1.w = pk2(s3.z, s3.w);
    uint4* d = (uint4*)dst;
    d[0] = o0; d[1] = o1;
}

// ---------------------------------------------------------------------------
// fp16 GEMM (256 threads, 8 warps), TM-parametrized warp tile (TM/4)x64,
// 3-stage cp.async pipeline, single __syncthreads per k-chunk, ldmatrix.
// TM=128: qkv (grid 12x32).  TM=64: outproj (grid 4x64 -> all SMs busy).
// EPI=0: scatter qkv PLAIN.  EPI=1: A := g_ao, write out + bias fp32.
// ---------------------------------------------------------------------------
#define GP 36
#define GEMM_SMEM(TM) (3 * ((TM) + 128) * GP * 4)

template <int TM, int NTOT, int EPI>
__global__ __launch_bounds__(256, 2) void gemm_h(const unsigned* __restrict__ A,
                                                 const unsigned* __restrict__ Wt,
                                                 const float* __restrict__ bias,
                                                 float* __restrict__ out)
{
    constexpr int MF = TM / 64;          // m-fragments per warp
    extern __shared__ unsigned gsm[];
    unsigned* As = gsm;                  // [3][TM][GP]
    unsigned* Bs = gsm + 3 * TM * GP;    // [3][128][GP]

    const int m0 = blockIdx.y * TM;
    const int n0 = blockIdx.x * 128;
    const int tid  = threadIdx.x;
    const int warp = tid >> 5, lane = tid & 31;
    const int g = lane >> 2, t = lane & 3;
    const int wm = warp >> 1, wn = warp & 1;

    const int arow = ((lane >> 3) & 1) * 8 + (lane & 7);
    const int acol = (lane >> 4) << 2;                    // uints
    const int brow = ((lane >> 4) << 3) + (lane & 7);
    const int bcol = ((lane >> 3) & 1) * 4;               // uints

    const unsigned* Ap = (EPI == 1) ? (const unsigned*)g_ao : A;

    float C[MF][8][4] = {};

    auto issue = [&](int ki, int buf) {
        int k0 = ki * 32;                       // uints
        unsigned* Ad = As + buf * TM * GP;
        unsigned* Bd = Bs + buf * 128 * GP;
        #pragma unroll
        for (int p = 0; p < TM / 32; p++) {
            int c = tid + p * 256;
            int r = c >> 3, col = (c & 7) * 4;
            CP16(sptr(&Ad[r * GP + col]), &Ap[(size_t)(m0 + r) * D2 + k0 + col]);
        }
        #pragma unroll
        for (int p = 0; p < 4; p++) {
            int c = tid + p * 256;
            int r = c >> 3, col = (c & 7) * 4;
            CP16(sptr(&Bd[r * GP + col]), &Wt[(size_t)(n0 + r) * D2 + k0 + col]);
        }
    };

    issue(0, 0); cp_commit();
    issue(1, 1); cp_commit();

    int buf = 0;
    for (int ki = 0; ki < 8; ki++) {
        // stage ki ready (ki+1 may be in flight); barrier also certifies all
        // warps done with chunk ki-1, whose stage (ki+2)%3 we overwrite below.
        cp_wait1();
        __syncthreads();

        const unsigned* Af = As + buf * TM * GP;
        const unsigned* Bf = Bs + buf * 128 * GP;
        #pragma unroll
        for (int ks = 0; ks < 4; ks++) {         // 4 k16 steps per chunk
            unsigned a[MF][4];
            #pragma unroll
            for (int mf = 0; mf < MF; mf++)
                ldsm4(a[mf][0], a[mf][1], a[mf][2], a[mf][3],
                      sptr(&Af[(wm * (TM / 4) + mf * 16 + arow) * GP + ks * 8 + acol]));
            #pragma unroll
            for (int f = 0; f < 4; f++) {
                unsigned d0, d1, d2, d3;
                ldsm4(d0, d1, d2, d3,
                      sptr(&Bf[(wn * 64 + 16 * f + brow) * GP + ks * 8 + bcol]));
                #pragma unroll
                for (int mf = 0; mf < MF; mf++) {
                    mma16(C[mf][2*f],   a[mf][0], a[mf][1], a[mf][2], a[mf][3], d0, d1);
                    mma16(C[mf][2*f+1], a[mf][0], a[mf][1], a[mf][2], a[mf][3], d2, d3);
                }
            }
        }

        if (ki + 2 < 8) {
            int nb = buf + 2; if (nb >= 3) nb -= 3;
            issue(ki + 2, nb);
        }
        cp_commit();
        if (++buf == 3) buf = 0;
    }

    const float qscale = 0.125f * LOG2E;

    if (EPI == 0) {
        __half* hv = (__half*)g_qkv;
        #pragma unroll
        for (int mf = 0; mf < MF; mf++) {
            int m = m0 + wm * (TM / 4) + mf * 16;
            #pragma unroll
            for (int nf = 0; nf < 8; nf++) {
                int n   = n0 + wn * 64 + nf * 8 + 2 * t;
                int sec = n >> 9;
                int h   = (n >> 6) & 7;
                int dh  = n & 63;
                #pragma unroll
                for (int rr = 0; rr < 2; rr++) {
                    int mm = m + g + rr * 8;
                    int b  = mm >> 11;
                    int l  = mm & 2047;
                    float c0v = C[mf][nf][rr * 2 + 0];
                    float c1v = C[mf][nf][rr * 2 + 1];
                    if (sec == 0) { c0v *= qscale; c1v *= qscale; }
                    if (sec < 2) {
                        g_qkv[(size_t)sec * QS_U
                              + (size_t)((b * H_ + h) * L_ + l) * 32 + (dh >> 1)] = pk2(c0v, c1v);
                    } else {
                        size_t vb2 = (size_t)2 * QS_U * 2
                                   + (size_t)(b * H_ + h) * L_ * DH_
                                   + (size_t)(l >> 6) * 4096 + (l & 63);
                        hv[vb2 + (size_t)dh * 64]       = __float2half_rn(c0v);
                        hv[vb2 + (size_t)(dh + 1) * 64] = __float2half_rn(c1v);
                    }
                }
            }
        }
    } else {
        #pragma unroll
        for (int mf = 0; mf < MF; mf++) {
            int m = m0 + wm * (TM / 4) + mf * 16;
            #pragma unroll
            for (int nf = 0; nf < 8; nf++) {
                int n = n0 + wn * 64 + nf * 8 + 2 * t;
                float b0v = bias[n], b1v = bias[n + 1];
                #pragma unroll
                for (int rr = 0; rr < 2; rr++) {
                    int mm = m + g + rr * 8;
                    float2 v;
                    v.x = C[mf][nf][rr * 2 + 0] + b0v;
                    v.y = C[mf][nf][rr * 2 + 1] + b1v;
                    *(float2*)&out[(size_t)mm * NTOT + n] = v;
                }
            }
        }
    }
}

// ---------------------------------------------------------------------------
// Flash attention (R12 form): 3-stage cp.async pipeline, single __syncthreads
// per tile, ldmatrix frags, register P, f16x2 exp, tensor-core row sums,
// rescale skipping, factored bias (softmax shift-invariant form).
// ---------------------------------------------------------------------------
#define KP 36
#define ATTN_SMEM ((6 * 64 * KP + 128 * KP) * 4 + 128 * 8 + 2 * 64 * 16)

__global__ __launch_bounds__(256, 2) void attn_h(const float* __restrict__ pos,
                                                 const float* __restrict__ log_sigma,
                                                 const float* __restrict__ gbias_p,
                                                 const int*   __restrict__ nsp)
{
    extern __shared__ unsigned smA[];
    unsigned* Ks = smA;                   // [3][64][KP]
    unsigned* Vs = smA + 3 * 64 * KP;     // [3][64][KP]  (V^T tiles)
    unsigned* Qs = smA + 6 * 64 * KP;     // [128][KP]
    float2* qpos = (float2*)(Qs + 128 * KP);     // 128
    float4* kq   = (float4*)(qpos + 128);        // [2][64]: kx, ky, nc2*|p|^2, 0

    const int i0 = blockIdx.x * 128;
    const int bh = blockIdx.y;
    const int b  = bh >> 3, h = bh & 7;
    const int Ls = *nsp;
    const float gb2 = (*gbias_p) * LOG2E;
    const float nc2 = -0.5f * __expf(-2.0f * log_sigma[h]) * LOG2E;

    const int tid  = threadIdx.x;
    const int warp = tid >> 5, lane = tid & 31;
    const int g = lane >> 2, t = lane & 3;
    const int wr = warp * 16;

    const unsigned* qb = g_qkv + (size_t)(b * H_ + h) * L_ * 32;
    const unsigned* kb = g_qkv + (size_t)QS_U + (size_t)(b * H_ + h) * L_ * 32;
    const unsigned* vb = g_qkv + 2 * (size_t)QS_U + (size_t)(b * H_ + h) * L_ * 32;

    // Stage Q tile + qpos + kq tile 0
    #pragma unroll
    for (int p = 0; p < 4; p++) {
        int c = tid + p * 256;
        int r = c >> 3, c4 = (c & 7) * 4;
        *(uint4*)&Qs[r * KP + c4] = *(const uint4*)&qb[(size_t)(i0 + r) * 32 + c4];
    }
    if (tid < 128) {
        int iG = i0 + tid;
        float2 v = make_float2(0.f, 0.f);
        if (iG < Ls) v = *(const float2*)&pos[(size_t)(b * Ls + iG) * 2];
        qpos[tid] = v;
    }
    if (tid < 64) {
        float2 p = make_float2(0.f, 0.f);
        if (tid < Ls) p = *(const float2*)&pos[(size_t)(b * Ls + tid) * 2];
        kq[tid] = make_float4(p.x, p.y, nc2 * (p.x * p.x + p.y * p.y), 0.f);
    }

    auto issue = [&](int jt, int buf) {
        const unsigned* kt = kb + (size_t)jt * 2048;
        const unsigned* vt = vb + (size_t)jt * 2048;
        unsigned* Kd = Ks + buf * 64 * KP;
        unsigned* Vd = Vs + buf * 64 * KP;
        #pragma unroll
        for (int p = 0; p < 2; p++) {
            int c = tid + p * 256;
            int r = c >> 3, c4 = (c & 7) * 4;
            CP16(sptr(&Kd[r * KP + c4]), kt + r * 32 + c4);
            CP16(sptr(&Vd[r * KP + c4]), vt + r * 32 + c4);
        }
    };

    // Prologue: fill stages 0 and 1
    issue(0, 0); cp_commit();
    issue(1, 1); cp_commit();

    __syncthreads();   // Qs/qpos/kq visible

    // Q A-fragments via ldmatrix (once)
    unsigned qf[4][4];
    {
        int qrow = wr + ((lane >> 3) & 1) * 8 + (lane & 7);
        int qcol = (lane >> 4) << 2;
        #pragma unroll
        for (int ks = 0; ks < 4; ks++)
            ldsm4(qf[ks][0], qf[ks][1], qf[ks][2], qf[ks][3],
                  sptr(&Qs[qrow * KP + ks * 8 + qcol]));
    }

    // Row constants for factored bias
    float cx0, cy0, cx1, cy1, ga0, ga1;
    bool iin0, iin1;
    {
        int r0 = i0 + wr + g;
        float2 p0 = qpos[wr + g], p1 = qpos[wr + g + 8];
        cx0 = -2.f * nc2 * p0.x; cy0 = -2.f * nc2 * p0.y;
        cx1 = -2.f * nc2 * p1.x; cy1 = -2.f * nc2 * p1.y;
        ga0 = gb2 - nc2 * (p0.x * p0.x + p0.y * p0.y);
        ga1 = gb2 - nc2 * (p1.x * p1.x + p1.y * p1.y);
        iin0 = r0 < Ls; iin1 = (r0 + 8) < Ls;
    }

    const int lrow8 = ((lane >> 4) << 3) + (lane & 7);
    const int lsel  = ((lane >> 3) & 1) * 4;

    float O[8][4] = {};
    float O8[4] = {};
    float m0 = -1e30f, m1 = -1e30f;
    const bool i_allsp = (i0 + 128) <= Ls;
    const bool i_allout = i0 >= Ls;
    const unsigned ones2 = (g == 0) ? 0x3C003C00u : 0u;

    int buf = 0;
    for (int jt = 0; jt < 32; jt++) {
        // Single barrier per tile: wait makes stage jt visible; the barrier
        // publishes it CTA-wide and certifies all warps finished tile jt-1
        // (whose stage (jt+2)%3 we overwrite at the end).
        cp_wait1();
        __syncthreads();

        bool pref = (jt + 1 < 32);
        float2 pp = make_float2(0.f, 0.f);
        if (pref && tid < 64) {
            int jG = (jt + 1) * 64 + tid;
            if (jG < Ls) pp = *(const float2*)&pos[(size_t)(b * Ls + jG) * 2];
        }

        const unsigned* Kf = Ks + buf * 64 * KP;
        const unsigned* Vf = Vs + buf * 64 * KP;
        const float4*   kc = kq + (jt & 1) * 64;
        const int j0 = jt * 64;

        // S = Q K^T
        float S[8][4] = {};
        #pragma unroll
        for (int f = 0; f < 4; f++) {
            #pragma unroll
            for (int ks = 0; ks < 4; ks++) {
                unsigned d0, d1, d2, d3;
                ldsm4(d0, d1, d2, d3,
                      sptr(&Kf[(16 * f + lrow8) * KP + 8 * ks + lsel]));
                mma16(S[2*f],   qf[ks][0], qf[ks][1], qf[ks][2], qf[ks][3], d0, d1);
                mma16(S[2*f+1], qf[ks][0], qf[ks][1], qf[ks][2], qf[ks][3], d2, d3);
            }
        }

        // Factored bias (scores shifted by -nc2|pi|^2; softmax-invariant)
        if (i_allsp && (j0 + 64) <= Ls) {
            #pragma unroll
            for (int nf = 0; nf < 8; nf++) {
                int c0 = nf * 8 + 2 * t;
                float4 k0 = kc[c0], k1 = kc[c0 + 1];
                S[nf][0] = fmaf(cx0, k0.x, fmaf(cy0, k0.y, S[nf][0] + k0.z));
                S[nf][1] = fmaf(cx0, k1.x, fmaf(cy0, k1.y, S[nf][1] + k1.z));
                S[nf][2] = fmaf(cx1, k0.x, fmaf(cy1, k0.y, S[nf][2] + k0.z));
                S[nf][3] = fmaf(cx1, k1.x, fmaf(cy1, k1.y, S[nf][3] + k1.z));
            }
        } else if (j0 >= Ls || i_allout) {
            #pragma unroll
            for (int nf = 0; nf < 8; nf++) {
                S[nf][0] += ga0; S[nf][1] += ga0; S[nf][2] += ga1; S[nf][3] += ga1;
            }
        } else {
            #pragma unroll
            for (int nf = 0; nf < 8; nf++) {
                int c0 = nf * 8 + 2 * t;
                int jg0 = j0 + c0;
                float4 k0 = kc[c0], k1 = kc[c0 + 1];
                bool jin0 = jg0 < Ls, jin1 = (jg0 + 1) < Ls;
                S[nf][0] = (iin0 && jin0)
                    ? fmaf(cx0, k0.x, fmaf(cy0, k0.y, S[nf][0] + k0.z)) : S[nf][0] + ga0;
                S[nf][1] = (iin0 && jin1)
                    ? fmaf(cx0, k1.x, fmaf(cy0, k1.y, S[nf][1] + k1.z)) : S[nf][1] + ga0;
                S[nf][2] = (iin1 && jin0)
                    ? fmaf(cx1, k0.x, fmaf(cy1, k0.y, S[nf][2] + k0.z)) : S[nf][2] + ga1;
                S[nf][3] = (iin1 && jin1)
                    ? fmaf(cx1, k1.x, fmaf(cy1, k1.y, S[nf][3] + k1.z)) : S[nf][3] + ga1;
            }
        }

        // Online softmax (base 2), rescale skipped when max unchanged
        float mx0 = -1e30f, mx1 = -1e30f;
        #pragma unroll
        for (int nf = 0; nf < 8; nf++) {
            mx0 = fmaxf(mx0, fmaxf(S[nf][0], S[nf][1]));
            mx1 = fmaxf(mx1, fmaxf(S[nf][2], S[nf][3]));
        }
        mx0 = fmaxf(mx0, __shfl_xor_sync(0xffffffffu, mx0, 1));
        mx0 = fmaxf(mx0, __shfl_xor_sync(0xffffffffu, mx0, 2));
        mx1 = fmaxf(mx1, __shfl_xor_sync(0xffffffffu, mx1, 1));
        mx1 = fmaxf(mx1, __shfl_xor_sync(0xffffffffu, mx1, 2));
        float mn0 = fmaxf(m0, mx0), mn1 = fmaxf(m1, mx1);
        bool stay = (mn0 == m0) && (mn1 == m1);
        if (!__all_sync(0xffffffffu, stay)) {
            float a0 = ex2(m0 - mn0), a1 = ex2(m1 - mn1);
            #pragma unroll
            for (int df = 0; df < 8; df++) {
                O[df][0] *= a0; O[df][1] *= a0; O[df][2] *= a1; O[df][3] *= a1;
            }
            O8[0] *= a0; O8[1] *= a0; O8[2] *= a1; O8[3] *= a1;
        }
        m0 = mn0; m1 = mn1;

        // P = 2^(S-m) packed half2 — directly the PV A-fragments
        unsigned ph[8], phh[8];
        #pragma unroll
        for (int nf = 0; nf < 8; nf++) {
            float e0 = S[nf][0] - m0, e1 = S[nf][1] - m0;
            float e2 = S[nf][2] - m1, e3 = S[nf][3] - m1;
            ph[nf]  = ex2h2(pkcvt(e1, e0));
            phh[nf] = ex2h2(pkcvt(e3, e2));
        }

        // O += P V
        #pragma unroll
        for (int f = 0; f < 4; f++) {
            #pragma unroll
            for (int ks = 0; ks < 4; ks++) {
                unsigned d0, d1, d2, d3;
                ldsm4(d0, d1, d2, d3,
                      sptr(&Vf[(16 * f + lrow8) * KP + 8 * ks + lsel]));
                mma16(O[2*f],   ph[2*ks], phh[2*ks], ph[2*ks+1], phh[2*ks+1], d0, d1);
                mma16(O[2*f+1], ph[2*ks], phh[2*ks], ph[2*ks+1], phh[2*ks+1], d2, d3);
            }
        }
        #pragma unroll
        for (int ks = 0; ks < 4; ks++)
            mma16(O8, ph[2*ks], phh[2*ks], ph[2*ks+1], phh[2*ks+1], ones2, ones2);

        // publish next tile's kq (read at jt+1 after its top barrier)
        if (pref && tid < 64)
            kq[((jt + 1) & 1) * 64 + tid] =
                make_float4(pp.x, pp.y, nc2 * (pp.x * pp.x + pp.y * pp.y), 0.f);

        // issue stage jt+2 (overwrites tile jt-1's stage; safe — everyone
        // passed this tile's top barrier). Unconditional commit keeps the
        // group count uniform for cp_wait1.
        if (jt + 2 < 32) {
            int nb = buf + 2; if (nb >= 3) nb -= 3;
            issue(jt + 2, nb);
        }
        cp_commit();

        if (++buf == 3) buf = 0;
    }

    // l from t=0 lane of each quad; normalize; write g_ao PLAIN
    float l0 = __shfl_sync(0xffffffffu, O8[0], lane & ~3);
    float l1 = __shfl_sync(0xffffffffu, O8[2], lane & ~3);
    float il0 = 1.f / l0, il1 = 1.f / l1;
    int r0 = i0 + wr + g, r1 = r0 + 8;
    #pragma unroll
    for (int df = 0; df < 8; df++) {
        int col = df * 4 + t;
        g_ao[(size_t)(b * L_ + r0) * D2 + h * 32 + col] = pk2(O[df][0] * il0, O[df][1] * il0);
        g_ao[(size_t)(b * L_ + r1) * D2 + h * 32 + col] = pk2(O[df][2] * il1, O[df][3] * il1);
    }
}

// ---------------------------------------------------------------------------
extern "C" void kernel_launch(void* const* d_in, const int* in_sizes, int n_in,
                              void* d_out, int out_size)
{
    const float* x     = (const float*)d_in[0];
    const float* pos   = (const float*)d_in[1];
    const float* wqkv  = (const float*)d_in[2];
    const float* wout  = (const float*)d_in[3];
    const float* bout  = (const float*)d_in[4];
    const float* lsig  = (const float*)d_in[5];
    const float* gbias = (const float*)d_in[6];
    const int*   nsp   = (const int*)d_in[7];
    float* out = (float*)d_out;

    unsigned *p_xt, *p_w1, *p_w2;
    cudaGetSymbolAddress((void**)&p_xt, g_xt);
    cudaGetSymbolAddress((void**)&p_w1, g_w1);
    cudaGetSymbolAddress((void**)&p_w2, g_w2);

    cudaFuncSetAttribute(attn_h, cudaFuncAttributeMaxDynamicSharedMemorySize, ATTN_SMEM);
    cudaFuncSetAttribute(gemm_h<128, NQKV, 0>, cudaFuncAttributeMaxDynamicSharedMemorySize, GEMM_SMEM(128));
    cudaFuncSetAttribute(gemm_h<64, D_, 1>, cudaFuncAttributeMaxDynamicSharedMemorySize, GEMM_SMEM(64));

    prep_all<<<(N16_TOT + 255) / 256, 256>>>(x, wqkv, wout);
    gemm_h<128, NQKV, 0><<<dim3(NQKV / 128, M_ / 128), 256, GEMM_SMEM(128)>>>(p_xt, p_w1, nullptr, nullptr);
    attn_h<<<dim3(L_ / 128, B_ * H_), 256, ATTN_SMEM>>>(pos, lsig, gbias, nsp);
    gemm_h<64, D_, 1><<<dim3(D_ / 128, M_ / 64), 256, GEMM_SMEM(64)>>>(nullptr, p_w2, bout, out);
}

// round 16
// speedup vs baseline: 1.0213x; 1.0194x over previous
#include <cuda_runtime.h>
#include <cuda_fp16.h>

#define B_   2
#define H_   8
#define L_   2048
#define DH_  64
#define D_   512
#define M_   4096
#define NQKV 1536
#define D2   256                 // uints (half2) per row of a D_-wide matrix
#define QS_U 1048576             // uints per qkv section: B*H*L*DH/2
#define LOG2E 1.4426950408889634f

// Scratch (device globals; no allocations allowed). ALL layouts PLAIN
// (ldmatrix handles fragment shuffling).
// q (prescaled by 0.125*log2e), k: [B,H,L, 32 uints]
// v: transposed per 64-key tile [B,H,L/64, 64 dh rows, 64 key halves]
__device__ unsigned g_qkv[3 * QS_U];
__device__ unsigned g_ao[M_ * D2];       // attn out (plain)
__device__ unsigned g_xt[M_ * D2];       // x converted
__device__ unsigned g_w1[NQKV * D2];     // w_qkv converted
__device__ unsigned g_w2[D_ * D2];       // w_out converted

__device__ __forceinline__ unsigned pk2(float a, float b) {
    __half2 h = __floats2half2_rn(a, b);       // low = a
    return *(unsigned*)&h;
}
__device__ __forceinline__ unsigned pkcvt(float hi, float lo) {
    unsigned r; asm("cvt.rn.f16x2.f32 %0, %1, %2;" : "=r"(r) : "f"(hi), "f"(lo)); return r;
}
__device__ __forceinline__ unsigned ex2h2(unsigned x) {
    unsigned r; asm("ex2.approx.f16x2 %0, %1;" : "=r"(r) : "r"(x)); return r;
}
__device__ __forceinline__ float ex2(float x) {
    float r; asm("ex2.approx.f32 %0, %1;" : "=f"(r) : "f"(x)); return r;
}
__device__ __forceinline__ unsigned sptr(const void* p) {
    return (unsigned)__cvta_generic_to_shared(p);
}
__device__ __forceinline__ void ldsm4(unsigned& d0, unsigned& d1, unsigned& d2, unsigned& d3,
                                      unsigned addr) {
    asm volatile("ldmatrix.sync.aligned.m8n8.x4.shared.b16 {%0,%1,%2,%3}, [%4];"
                 : "=r"(d0), "=r"(d1), "=r"(d2), "=r"(d3) : "r"(addr));
}
#define CP16(d, s) asm volatile("cp.async.cg.shared.global [%0], [%1], 16;" :: "r"(d), "l"(s) : "memory")
__device__ __forceinline__ void cp_commit() { asm volatile("cp.async.commit_group;" ::: "memory"); }
__device__ __forceinline__ void cp_wait0()  { asm volatile("cp.async.wait_group 0;" ::: "memory"); }
__device__ __forceinline__ void cp_wait1()  { asm volatile("cp.async.wait_group 1;" ::: "memory"); }

__device__ __forceinline__ void mma16(float* c,
                                      unsigned a0, unsigned a1, unsigned a2, unsigned a3,
                                      unsigned b0, unsigned b1) {
    asm volatile("mma.sync.aligned.m16n8k16.row.col.f32.f16.f16.f32 "
                 "{%0,%1,%2,%3}, {%4,%5,%6,%7}, {%8,%9}, {%0,%1,%2,%3};"
                 : "+f"(c[0]), "+f"(c[1]), "+f"(c[2]), "+f"(c[3])
                 : "r"(a0), "r"(a1), "r"(a2), "r"(a3), "r"(b0), "r"(b1));
}

// ---------------------------------------------------------------------------
// Fused prepass: fp32 -> half2 plain convert for x, w_qkv, w_out (one launch).
// ---------------------------------------------------------------------------
#define N16_X  (M_ * D_ / 16)
#define N16_W1 (NQKV * D_ / 16)
#define N16_W2 (D_ * D_ / 16)
#define N16_TOT (N16_X + N16_W1 + N16_W2)

__global__ __launch_bounds__(256) void prep_all(const float* __restrict__ x,
                                                const float* __restrict__ wqkv,
                                                const float* __restrict__ wout)
{
    int i = blockIdx.x * blockDim.x + threadIdx.x;
    if (i >= N16_TOT) return;
    const float* src;
    unsigned* dst;
    if (i < N16_X)                { src = x    + (size_t)i * 16;            dst = g_xt + (size_t)i * 8; }
    else if (i < N16_X + N16_W1)  { size_t j = i - N16_X;
                                    src = wqkv + j * 16;                     dst = g_w1 + j * 8; }
    else                          { size_t j = i - N16_X - N16_W1;
                                    src = wout + j * 16;                     dst = g_w2 + j * 8; }
    const float4* s = (const float4*)src;
    float4 s0 = s[0], s1 = s[1], s2 = s[2], s3 = s[3];
    uint4 o0, o1;
    o0.x = pk2(s0.x, s0.y); o0.y = pk2(s0.z, s0.w);
    o0.z = pk2(s1.x, s1.y); o0.w = pk2(s1.z, s1.w);
    o1.x = pk2(s2.x, s2.y); o1.y = pk2(s2.z, s2.w);
    o1.z = pk2(s3.x, s3.y); o1.w = pk2(s3.z, s3.w);
    uint4* d = (uint4*)dst;
    d[0] = o0; d[1] = o1;
}

// ---------------------------------------------------------------------------
// fp16 GEMM (256 threads, 8 warps 4x2, warp tile 32x64), 3-stage cp.async
// pipeline, single __syncthreads per k-chunk, ldmatrix fragments. TM=128.
// EPI=0: scatter qkv PLAIN.  EPI=1: A := g_ao, write out + bias fp32.
// ---------------------------------------------------------------------------
#define GP 36
#define GEMM_SMEM (3 * (128 + 128) * GP * 4)

template <int NTOT, int EPI>
__global__ __launch_bounds__(256, 2) void gemm_h(const unsigned* __restrict__ A,
                                                 const unsigned* __restrict__ Wt,
                                                 const float* __restrict__ bias,
                                                 float* __restrict__ out)
{
    extern __shared__ unsigned gsm[];
    unsigned* As = gsm;                 // [3][128][GP]
    unsigned* Bs = gsm + 3 * 128 * GP;  // [3][128][GP]

    const int m0 = blockIdx.y * 128;
    const int n0 = blockIdx.x * 128;
    const int tid  = threadIdx.x;
    const int warp = tid >> 5, lane = tid & 31;
    const int g = lane >> 2, t = lane & 3;
    const int wm = warp >> 1, wn = warp & 1;

    const int arow = ((lane >> 3) & 1) * 8 + (lane & 7);
    const int acol = (lane >> 4) << 2;
    const int brow = ((lane >> 4) << 3) + (lane & 7);
    const int bcol = ((lane >> 3) & 1) * 4;

    const unsigned* Ap = (EPI == 1) ? (const unsigned*)g_ao : A;

    float C[2][8][4] = {};

    auto issue = [&](int ki, int buf) {
        int k0 = ki * 32;
        unsigned* Ad = As + buf * 128 * GP;
        unsigned* Bd = Bs + buf * 128 * GP;
        #pragma unroll
        for (int p = 0; p < 4; p++) {
            int c = tid + p * 256;
            int r = c >> 3, col = (c & 7) * 4;
            CP16(sptr(&Ad[r * GP + col]), &Ap[(size_t)(m0 + r) * D2 + k0 + col]);
            CP16(sptr(&Bd[r * GP + col]), &Wt[(size_t)(n0 + r) * D2 + k0 + col]);
        }
    };

    issue(0, 0); cp_commit();
    issue(1, 1); cp_commit();

    int buf = 0;
    for (int ki = 0; ki < 8; ki++) {
        cp_wait1();
        __syncthreads();

        const unsigned* Af = As + buf * 128 * GP;
        const unsigned* Bf = Bs + buf * 128 * GP;
        #pragma unroll
        for (int ks = 0; ks < 4; ks++) {
            unsigned a[2][4];
            #pragma unroll
            for (int mf = 0; mf < 2; mf++)
                ldsm4(a[mf][0], a[mf][1], a[mf][2], a[mf][3],
                      sptr(&Af[(wm * 32 + mf * 16 + arow) * GP + ks * 8 + acol]));
            #pragma unroll
            for (int f = 0; f < 4; f++) {
                unsigned d0, d1, d2, d3;
                ldsm4(d0, d1, d2, d3,
                      sptr(&Bf[(wn * 64 + 16 * f + brow) * GP + ks * 8 + bcol]));
                mma16(C[0][2*f],   a[0][0], a[0][1], a[0][2], a[0][3], d0, d1);
                mma16(C[0][2*f+1], a[0][0], a[0][1], a[0][2], a[0][3], d2, d3);
                mma16(C[1][2*f],   a[1][0], a[1][1], a[1][2], a[1][3], d0, d1);
                mma16(C[1][2*f+1], a[1][0], a[1][1], a[1][2], a[1][3], d2, d3);
            }
        }

        if (ki + 2 < 8) {
            int nb = buf + 2; if (nb >= 3) nb -= 3;
            issue(ki + 2, nb);
        }
        cp_commit();
        if (++buf == 3) buf = 0;
    }

    const float qscale = 0.125f * LOG2E;

    if (EPI == 0) {
        __half* hv = (__half*)g_qkv;
        #pragma unroll
        for (int mf = 0; mf < 2; mf++) {
            int m = m0 + wm * 32 + mf * 16;
            #pragma unroll
            for (int nf = 0; nf < 8; nf++) {
                int n   = n0 + wn * 64 + nf * 8 + 2 * t;
                int sec = n >> 9;
                int h   = (n >> 6) & 7;
                int dh  = n & 63;
                #pragma unroll
                for (int rr = 0; rr < 2; rr++) {
                    int mm = m + g + rr * 8;
                    int b  = mm >> 11;
                    int l  = mm & 2047;
                    float c0v = C[mf][nf][rr * 2 + 0];
                    float c1v = C[mf][nf][rr * 2 + 1];
                    if (sec == 0) { c0v *= qscale; c1v *= qscale; }
                    if (sec < 2) {
                        g_qkv[(size_t)sec * QS_U
                              + (size_t)((b * H_ + h) * L_ + l) * 32 + (dh >> 1)] = pk2(c0v, c1v);
                    } else {
                        size_t vb2 = (size_t)2 * QS_U * 2
                                   + (size_t)(b * H_ + h) * L_ * DH_
                                   + (size_t)(l >> 6) * 4096 + (l & 63);
                        hv[vb2 + (size_t)dh * 64]       = __float2half_rn(c0v);
                        hv[vb2 + (size_t)(dh + 1) * 64] = __float2half_rn(c1v);
                    }
                }
            }
        }
    } else {
        #pragma unroll
        for (int mf = 0; mf < 2; mf++) {
            int m = m0 + wm * 32 + mf * 16;
            #pragma unroll
            for (int nf = 0; nf < 8; nf++) {
                int n = n0 + wn * 64 + nf * 8 + 2 * t;
                float b0v = bias[n], b1v = bias[n + 1];
                #pragma unroll
                for (int rr = 0; rr < 2; rr++) {
                    int mm = m + g + rr * 8;
                    float2 v;
                    v.x = C[mf][nf][rr * 2 + 0] + b0v;
                    v.y = C[mf][nf][rr * 2 + 1] + b1v;
                    *(float2*)&out[(size_t)mm * NTOT + n] = v;
                }
            }
        }
    }
}

// ---------------------------------------------------------------------------
// Flash attention: 128-key stages, 2-stage cp.async pipeline (wait0 at top,
// issue next stage right after the barrier -> full load/compute overlap),
// each stage processed as two 64-key sub-passes. 16 barriers total.
// ldmatrix frags, register P, f16x2 exp, tensor-core row sums, rescale
// skipping, factored bias (softmax shift-invariant form).
// ---------------------------------------------------------------------------
#define KP 36
#define ATTN_SMEM ((4 * 128 * KP + 128 * KP) * 4 + 128 * 8 + 2 * 128 * 16)

__global__ __launch_bounds__(256, 2) void attn_h(const float* __restrict__ pos,
                                                 const float* __restrict__ log_sigma,
                                                 const float* __restrict__ gbias_p,
                                                 const int*   __restrict__ nsp)
{
    extern __shared__ unsigned smA[];
    unsigned* Ks = smA;                    // [2][128][KP]   (rows = keys)
    unsigned* Vs = smA + 2 * 128 * KP;     // [2][2][64][KP] (V^T sub-tiles)
    unsigned* Qs = smA + 4 * 128 * KP;     // [128][KP]
    float2* qpos = (float2*)(Qs + 128 * KP);     // 128
    float4* kq   = (float4*)(qpos + 128);        // [2][128]: kx, ky, nc2*|p|^2, 0

    const int i0 = blockIdx.x * 128;
    const int bh = blockIdx.y;
    const int b  = bh >> 3, h = bh & 7;
    const int Ls = *nsp;
    const float gb2 = (*gbias_p) * LOG2E;
    const float nc2 = -0.5f * __expf(-2.0f * log_sigma[h]) * LOG2E;

    const int tid  = threadIdx.x;
    const int warp = tid >> 5, lane = tid & 31;
    const int g = lane >> 2, t = lane & 3;
    const int wr = warp * 16;

    const unsigned* qb = g_qkv + (size_t)(b * H_ + h) * L_ * 32;
    const unsigned* kb = g_qkv + (size_t)QS_U + (size_t)(b * H_ + h) * L_ * 32;
    const unsigned* vb = g_qkv + 2 * (size_t)QS_U + (size_t)(b * H_ + h) * L_ * 32;

    // Stage Q tile + qpos + kq stage 0 (keys 0..127)
    #pragma unroll
    for (int p = 0; p < 4; p++) {
        int c = tid + p * 256;
        int r = c >> 3, c4 = (c & 7) * 4;
        *(uint4*)&Qs[r * KP + c4] = *(const uint4*)&qb[(size_t)(i0 + r) * 32 + c4];
    }
    if (tid < 128) {
        int iG = i0 + tid;
        float2 v = make_float2(0.f, 0.f);
        if (iG < Ls) v = *(const float2*)&pos[(size_t)(b * Ls + iG) * 2];
        qpos[tid] = v;
        float2 p = make_float2(0.f, 0.f);
        if (tid < Ls) p = *(const float2*)&pos[(size_t)(b * Ls + tid) * 2];
        kq[tid] = make_float4(p.x, p.y, nc2 * (p.x * p.x + p.y * p.y), 0.f);
    }

    // issue a full 128-key stage: K rows = keys; V = two 64-key V^T tiles
    auto issue = [&](int jt, int s) {
        const unsigned* kt = kb + (size_t)jt * 4096;    // 128 rows x 32 uints
        const unsigned* vt = vb + (size_t)jt * 4096;    // two 2048-uint tiles
        unsigned* Kd = Ks + s * 128 * KP;
        unsigned* Vd = Vs + s * 128 * KP;
        #pragma unroll
        for (int p = 0; p < 4; p++) {
            int idx = tid + p * 256;
            int r = idx >> 3, c4 = (idx & 7) * 4;
            CP16(sptr(&Kd[r * KP + c4]), kt + r * 32 + c4);
        }
        #pragma unroll
        for (int p = 0; p < 4; p++) {
            int idx = tid + p * 256;
            int sub = idx >> 9, w = idx & 511;
            int r = w >> 3, c4 = (w & 7) * 4;
            CP16(sptr(&Vd[sub * 64 * KP + r * KP + c4]), vt + sub * 2048 + r * 32 + c4);
        }
    };

    issue(0, 0); cp_commit();

    __syncthreads();   // Qs/qpos/kq visible

    // Q A-fragments via ldmatrix (once)
    unsigned qf[4][4];
    {
        int qrow = wr + ((lane >> 3) & 1) * 8 + (lane & 7);
        int qcol = (lane >> 4) << 2;
        #pragma unroll
        for (int ks = 0; ks < 4; ks++)
            ldsm4(qf[ks][0], qf[ks][1], qf[ks][2], qf[ks][3],
                  sptr(&Qs[qrow * KP + ks * 8 + qcol]));
    }

    // Row constants for factored bias
    float cx0, cy0, cx1, cy1, ga0, ga1;
    bool iin0, iin1;
    {
        int r0 = i0 + wr + g;
        float2 p0 = qpos[wr + g], p1 = qpos[wr + g + 8];
        cx0 = -2.f * nc2 * p0.x; cy0 = -2.f * nc2 * p0.y;
        cx1 = -2.f * nc2 * p1.x; cy1 = -2.f * nc2 * p1.y;
        ga0 = gb2 - nc2 * (p0.x * p0.x + p0.y * p0.y);
        ga1 = gb2 - nc2 * (p1.x * p1.x + p1.y * p1.y);
        iin0 = r0 < Ls; iin1 = (r0 + 8) < Ls;
    }

    const int lrow8 = ((lane >> 4) << 3) + (lane & 7);
    const int lsel  = ((lane >> 3) & 1) * 4;

    float O[8][4] = {};
    float O8[4] = {};
    float m0 = -1e30f, m1 = -1e30f;
    const bool i_allsp = (i0 + 128) <= Ls;
    const bool i_allout = i0 >= Ls;
    const unsigned ones2 = (g == 0) ? 0x3C003C00u : 0u;

    for (int jt = 0; jt < 16; jt++) {
        // wait for stage jt; barrier also certifies all warps consumed stage
        // jt-1 (same slot as jt+1), so issuing jt+1 below is safe.
        cp_wait0();
        __syncthreads();

        bool pref = (jt + 1 < 16);
        float2 pp = make_float2(0.f, 0.f);
        if (pref && tid < 128) {
            int jG = (jt + 1) * 128 + tid;
            if (jG < Ls) pp = *(const float2*)&pos[(size_t)(b * Ls + jG) * 2];
        }
        if (pref) issue(jt + 1, (jt + 1) & 1);
        cp_commit();

        #pragma unroll
        for (int sub = 0; sub < 2; sub++) {
            const unsigned* Kf = Ks + (jt & 1) * 128 * KP + sub * 64 * KP;
            const unsigned* Vf = Vs + (jt & 1) * 128 * KP + sub * 64 * KP;
            const float4*   kc = kq + (jt & 1) * 128 + sub * 64;
            const int j0 = jt * 128 + sub * 64;

            // S = Q K^T
            float S[8][4] = {};
            #pragma unroll
            for (int f = 0; f < 4; f++) {
                #pragma unroll
                for (int ks = 0; ks < 4; ks++) {
                    unsigned d0, d1, d2, d3;
                    ldsm4(d0, d1, d2, d3,
                          sptr(&Kf[(16 * f + lrow8) * KP + 8 * ks + lsel]));
                    mma16(S[2*f],   qf[ks][0], qf[ks][1], qf[ks][2], qf[ks][3], d0, d1);
                    mma16(S[2*f+1], qf[ks][0], qf[ks][1], qf[ks][2], qf[ks][3], d2, d3);
                }
            }

            // Factored bias (softmax shift-invariant form)
            if (i_allsp && (j0 + 64) <= Ls) {
                #pragma unroll
                for (int nf = 0; nf < 8; nf++) {
                    int c0 = nf * 8 + 2 * t;
                    float4 k0 = kc[c0], k1 = kc[c0 + 1];
                    S[nf][0] = fmaf(cx0, k0.x, fmaf(cy0, k0.y, S[nf][0] + k0.z));
                    S[nf][1] = fmaf(cx0, k1.x, fmaf(cy0, k1.y, S[nf][1] + k1.z));
                    S[nf][2] = fmaf(cx1, k0.x, fmaf(cy1, k0.y, S[nf][2] + k0.z));
                    S[nf][3] = fmaf(cx1, k1.x, fmaf(cy1, k1.y, S[nf][3] + k1.z));
                }
            } else if (j0 >= Ls || i_allout) {
                #pragma unroll
                for (int nf = 0; nf < 8; nf++) {
                    S[nf][0] += ga0; S[nf][1] += ga0; S[nf][2] += ga1; S[nf][3] += ga1;
                }
            } else {
                #pragma unroll
                for (int nf = 0; nf < 8; nf++) {
                    int c0 = nf * 8 + 2 * t;
                    int jg0 = j0 + c0;
                    float4 k0 = kc[c0], k1 = kc[c0 + 1];
                    bool jin0 = jg0 < Ls, jin1 = (jg0 + 1) < Ls;
                    S[nf][0] = (iin0 && jin0)
                        ? fmaf(cx0, k0.x, fmaf(cy0, k0.y, S[nf][0] + k0.z)) : S[nf][0] + ga0;
                    S[nf][1] = (iin0 && jin1)
                        ? fmaf(cx0, k1.x, fmaf(cy0, k1.y, S[nf][1] + k1.z)) : S[nf][1] + ga0;
                    S[nf][2] = (iin1 && jin0)
                        ? fmaf(cx1, k0.x, fmaf(cy1, k0.y, S[nf][2] + k0.z)) : S[nf][2] + ga1;
                    S[nf][3] = (iin1 && jin1)
                        ? fmaf(cx1, k1.x, fmaf(cy1, k1.y, S[nf][3] + k1.z)) : S[nf][3] + ga1;
                }
            }

            // Online softmax (base 2), rescale skipped when max unchanged
            float mx0 = -1e30f, mx1 = -1e30f;
            #pragma unroll
            for (int nf = 0; nf < 8; nf++) {
                mx0 = fmaxf(mx0, fmaxf(S[nf][0], S[nf][1]));
                mx1 = fmaxf(mx1, fmaxf(S[nf][2], S[nf][3]));
            }
            mx0 = fmaxf(mx0, __shfl_xor_sync(0xffffffffu, mx0, 1));
            mx0 = fmaxf(mx0, __shfl_xor_sync(0xffffffffu, mx0, 2));
            mx1 = fmaxf(mx1, __shfl_xor_sync(0xffffffffu, mx1, 1));
            mx1 = fmaxf(mx1, __shfl_xor_sync(0xffffffffu, mx1, 2));
            float mn0 = fmaxf(m0, mx0), mn1 = fmaxf(m1, mx1);
            bool stay = (mn0 == m0) && (mn1 == m1);
            if (!__all_sync(0xffffffffu, stay)) {
                float a0 = ex2(m0 - mn0), a1 = ex2(m1 - mn1);
                #pragma unroll
                for (int df = 0; df < 8; df++) {
                    O[df][0] *= a0; O[df][1] *= a0; O[df][2] *= a1; O[df][3] *= a1;
                }
                O8[0] *= a0; O8[1] *= a0; O8[2] *= a1; O8[3] *= a1;
            }
            m0 = mn0; m1 = mn1;

            // P = 2^(S-m) packed half2 — directly the PV A-fragments
            unsigned ph[8], phh[8];
            #pragma unroll
            for (int nf = 0; nf < 8; nf++) {
                float e0 = S[nf][0] - m0, e1 = S[nf][1] - m0;
                float e2 = S[nf][2] - m1, e3 = S[nf][3] - m1;
                ph[nf]  = ex2h2(pkcvt(e1, e0));
                phh[nf] = ex2h2(pkcvt(e3, e2));
            }

            // O += P V
            #pragma unroll
            for (int f = 0; f < 4; f++) {
                #pragma unroll
                for (int ks = 0; ks < 4; ks++) {
                    unsigned d0, d1, d2, d3;
                    ldsm4(d0, d1, d2, d3,
                          sptr(&Vf[(16 * f + lrow8) * KP + 8 * ks + lsel]));
                    mma16(O[2*f],   ph[2*ks], phh[2*ks], ph[2*ks+1], phh[2*ks+1], d0, d1);
                    mma16(O[2*f+1], ph[2*ks], phh[2*ks], ph[2*ks+1], phh[2*ks+1], d2, d3);
                }
            }
            #pragma unroll
            for (int ks = 0; ks < 4; ks++)
                mma16(O8, ph[2*ks], phh[2*ks], ph[2*ks+1], phh[2*ks+1], ones2, ones2);
        }

        // publish next stage's kq (slot (jt+1)&1 was last read during jt-1;
        // reads at jt+1 are ordered by its top barrier)
        if (pref && tid < 128)
            kq[((jt + 1) & 1) * 128 + tid] =
                make_float4(pp.x, pp.y, nc2 * (pp.x * pp.x + pp.y * pp.y), 0.f);
    }

    // l from t=0 lane of each quad; normalize; write g_ao PLAIN
    float l0 = __shfl_sync(0xffffffffu, O8[0], lane & ~3);
    float l1 = __shfl_sync(0xffffffffu, O8[2], lane & ~3);
    float il0 = 1.f / l0, il1 = 1.f / l1;
    int r0 = i0 + wr + g, r1 = r0 + 8;
    #pragma unroll
    for (int df = 0; df < 8; df++) {
        int col = df * 4 + t;
        g_ao[(size_t)(b * L_ + r0) * D2 + h * 32 + col] = pk2(O[df][0] * il0, O[df][1] * il0);
        g_ao[(size_t)(b * L_ + r1) * D2 + h * 32 + col] = pk2(O[df][2] * il1, O[df][3] * il1);
    }
}

// ---------------------------------------------------------------------------
extern "C" void kernel_launch(void* const* d_in, const int* in_sizes, int n_in,
                              void* d_out, int out_size)
{
    const float* x     = (const float*)d_in[0];
    const float* pos   = (const float*)d_in[1];
    const float* wqkv  = (const float*)d_in[2];
    const float* wout  = (const float*)d_in[3];
    const float* bout  = (const float*)d_in[4];
    const float* lsig  = (const float*)d_in[5];
    const float* gbias = (const float*)d_in[6];
    const int*   nsp   = (const int*)d_in[7];
    float* out = (float*)d_out;

    unsigned *p_xt, *p_w1, *p_w2;
    cudaGetSymbolAddress((void**)&p_xt, g_xt);
    cudaGetSymbolAddress((void**)&p_w1, g_w1);
    cudaGetSymbolAddress((void**)&p_w2, g_w2);

    cudaFuncSetAttribute(attn_h, cudaFuncAttributeMaxDynamicSharedMemorySize, ATTN_SMEM);
    cudaFuncSetAttribute(gemm_h<NQKV, 0>, cudaFuncAttributeMaxDynamicSharedMemorySize, GEMM_SMEM);
    cudaFuncSetAttribute(gemm_h<D_, 1>, cudaFuncAttributeMaxDynamicSharedMemorySize, GEMM_SMEM);

    prep_all<<<(N16_TOT + 255) / 256, 256>>>(x, wqkv, wout);
    gemm_h<NQKV, 0><<<dim3(NQKV / 128, M_ / 128), 256, GEMM_SMEM>>>(p_xt, p_w1, nullptr, nullptr);
    attn_h<<<dim3(L_ / 128, B_ * H_), 256, ATTN_SMEM>>>(pos, lsig, gbias, nsp);
    gemm_h<D_, 1><<<dim3(D_ / 128, M_ / 128), 256, GEMM_SMEM>>>(nullptr, p_w2, bout, out);
}